// round 1
// baseline (speedup 1.0000x reference)
#include <cuda_runtime.h>

// Real solid harmonics, max_l = 6, factored form:
//   out[l(l+1)+m] = ns[l(l+1)+m] * P_{l,|m|}(z, w) * (A_|m| or B_|m|)
// with w = x^2+y^2, A_m + i B_m = (x + i y)^m,
//   P_{l,a} = sum_t (-1)^t 4^{-t} C(l,t) C(l-t, a+t) w^t z^{l-a-2t}
// (exact algebraic factorization of the reference's monomial table).

#define BLK 128
#define NOUT 49

__global__ __launch_bounds__(BLK) void rsh_kernel(
    const float* __restrict__ xyz,
    const float* __restrict__ ns,
    float* __restrict__ out,
    int N)
{
    __shared__ float sh[BLK * NOUT];   // staging: input (first 384 floats), then outputs
    __shared__ float sns[NOUT];

    const int tid = threadIdx.x;
    const int base = blockIdx.x * BLK;
    int npts = N - base;
    if (npts > BLK) npts = BLK;

    if (tid < NOUT) sns[tid] = ns[tid];

    // ---- coalesced input stage: xyz[base*3 .. base*3 + npts*3) into sh ----
    if (npts == BLK) {
        const float4* in4 = (const float4*)(xyz + (size_t)base * 3);
        float4* s4 = (float4*)sh;
        #pragma unroll
        for (int i = tid; i < BLK * 3 / 4; i += BLK) s4[i] = in4[i];
    } else {
        for (int i = tid; i < npts * 3; i += BLK) sh[i] = xyz[(size_t)base * 3 + i];
    }
    __syncthreads();

    float x = 0.f, y = 0.f, z = 0.f;
    if (tid < npts) {
        x = sh[tid * 3 + 0];
        y = sh[tid * 3 + 1];
        z = sh[tid * 3 + 2];
    }
    __syncthreads();   // done reading input stage before overwriting sh

    if (tid < npts) {
        const float w  = x * x + y * y;
        const float z2 = z * z;
        const float z4 = z2 * z2;
        const float z6 = z4 * z2;
        const float w2 = w * w;
        const float w3 = w2 * w;

        // A_m + i B_m = (x + i y)^m
        const float A1 = x, B1 = y;
        const float A2 = x * A1 - y * B1;
        const float B2 = x * B1 + y * A1;
        const float A3 = x * A2 - y * B2;
        const float B3 = x * B2 + y * A2;
        const float A4 = x * A3 - y * B3;
        const float B4 = x * B3 + y * A3;
        const float A5 = x * A4 - y * B4;
        const float B5 = x * B4 + y * A4;
        const float A6 = x * A5 - y * B5;
        const float B6 = x * B5 + y * A5;

        // P_{l,|m|}
        const float P20 = z2 - 0.5f * w;
        const float P21 = 2.f * z;
        const float P30 = z * (z2 - 1.5f * w);
        const float P31 = 3.f * z2 - 0.75f * w;
        const float P32 = 3.f * z;
        const float P40 = z4 - 3.f * w * z2 + 0.375f * w2;
        const float P41 = z * (4.f * z2 - 3.f * w);
        const float P42 = 6.f * z2 - w;
        const float P43 = 4.f * z;
        const float P50 = z * (z4 - 5.f * w * z2 + 1.875f * w2);
        const float P51 = 5.f * z4 - 7.5f * w * z2 + 0.625f * w2;
        const float P52 = z * (10.f * z2 - 5.f * w);
        const float P53 = 10.f * z2 - 1.25f * w;
        const float P54 = 5.f * z;
        const float P60 = z6 - 7.5f * w * z4 + 5.625f * w2 * z2 - 0.3125f * w3;
        const float P61 = z * (6.f * z4 - 15.f * w * z2 + 3.75f * w2);
        const float P62 = 15.f * z4 - 15.f * w * z2 + 0.9375f * w2;
        const float P63 = z * (20.f * z2 - 7.5f * w);
        const float P64 = 15.f * z2 - 1.5f * w;
        const float P65 = 6.f * z;

        float* o = &sh[tid * NOUT];
        // l = 0
        o[0]  = sns[0];
        // l = 1
        o[1]  = sns[1]  * y;
        o[2]  = sns[2]  * z;
        o[3]  = sns[3]  * x;
        // l = 2
        o[4]  = sns[4]  * B2;
        o[5]  = sns[5]  * (P21 * B1);
        o[6]  = sns[6]  * P20;
        o[7]  = sns[7]  * (P21 * A1);
        o[8]  = sns[8]  * A2;
        // l = 3
        o[9]  = sns[9]  * B3;
        o[10] = sns[10] * (P32 * B2);
        o[11] = sns[11] * (P31 * B1);
        o[12] = sns[12] * P30;
        o[13] = sns[13] * (P31 * A1);
        o[14] = sns[14] * (P32 * A2);
        o[15] = sns[15] * A3;
        // l = 4
        o[16] = sns[16] * B4;
        o[17] = sns[17] * (P43 * B3);
        o[18] = sns[18] * (P42 * B2);
        o[19] = sns[19] * (P41 * B1);
        o[20] = sns[20] * P40;
        o[21] = sns[21] * (P41 * A1);
        o[22] = sns[22] * (P42 * A2);
        o[23] = sns[23] * (P43 * A3);
        o[24] = sns[24] * A4;
        // l = 5
        o[25] = sns[25] * B5;
        o[26] = sns[26] * (P54 * B4);
        o[27] = sns[27] * (P53 * B3);
        o[28] = sns[28] * (P52 * B2);
        o[29] = sns[29] * (P51 * B1);
        o[30] = sns[30] * P50;
        o[31] = sns[31] * (P51 * A1);
        o[32] = sns[32] * (P52 * A2);
        o[33] = sns[33] * (P53 * A3);
        o[34] = sns[34] * (P54 * A4);
        o[35] = sns[35] * A5;
        // l = 6
        o[36] = sns[36] * B6;
        o[37] = sns[37] * (P65 * B5);
        o[38] = sns[38] * (P64 * B4);
        o[39] = sns[39] * (P63 * B3);
        o[40] = sns[40] * (P62 * B2);
        o[41] = sns[41] * (P61 * B1);
        o[42] = sns[42] * P60;
        o[43] = sns[43] * (P61 * A1);
        o[44] = sns[44] * (P62 * A2);
        o[45] = sns[45] * (P63 * A3);
        o[46] = sns[46] * (P64 * A4);
        o[47] = sns[47] * (P65 * A5);
        o[48] = sns[48] * A6;
    }
    __syncthreads();

    // ---- coalesced output flush ----
    const size_t obase = (size_t)base * NOUT;
    if (npts == BLK) {
        float4* o4 = (float4*)(out + obase);
        const float4* s4 = (const float4*)sh;
        #pragma unroll
        for (int i = tid; i < BLK * NOUT / 4; i += BLK) o4[i] = s4[i];
    } else {
        const int total = npts * NOUT;
        for (int i = tid; i < total; i += BLK) out[obase + i] = sh[i];
    }
}

extern "C" void kernel_launch(void* const* d_in, const int* in_sizes, int n_in,
                              void* d_out, int out_size)
{
    const float* xyz = (const float*)d_in[0];   // [N, 3] f32
    const float* ns  = (const float*)d_in[2];   // [49] f32 (ns_lms)
    float* out = (float*)d_out;                 // [N, 49] f32
    const int N = in_sizes[0] / 3;

    const int grid = (N + BLK - 1) / BLK;
    rsh_kernel<<<grid, BLK>>>(xyz, ns, out, N);
}

// round 3
// speedup vs baseline: 1.0598x; 1.0598x over previous
#include <cuda_runtime.h>

// Real solid harmonics, max_l = 6, factored form:
//   out[l(l+1)+m] = ns[l(l+1)+m] * P_{l,|m|}(z, w) * (A_|m| or B_|m|)
// with w = x^2+y^2, A_m + i B_m = (x + i y)^m.
// Two-round half-block staging (64 points / 12.5KB) to raise occupancy.

#define BLK 128
#define CH 64            // points per flush chunk
#define NOUT 49

__global__ __launch_bounds__(BLK, 10) void rsh_kernel(
    const float* __restrict__ xyz,
    const float* __restrict__ ns,
    float* __restrict__ out,
    int N)
{
    __shared__ float sh[CH * NOUT];   // 12544 B staging
    __shared__ float sns[NOUT];

    const int tid = threadIdx.x;
    const int base = blockIdx.x * BLK;
    const int pt = base + tid;

    if (tid < NOUT) sns[tid] = ns[tid];

    // direct (L1-cached) input load; 384B/warp footprint
    float x = 0.f, y = 0.f, z = 0.f;
    if (pt < N) {
        x = __ldg(&xyz[(size_t)pt * 3 + 0]);
        y = __ldg(&xyz[(size_t)pt * 3 + 1]);
        z = __ldg(&xyz[(size_t)pt * 3 + 2]);
    }
    __syncthreads();   // sns visible

    #pragma unroll
    for (int r = 0; r < 2; r++) {
        // ---- compute + stage: half-block r only ----
        if ((tid >> 6) == r && pt < N) {
            const float w  = x * x + y * y;
            const float z2 = z * z;
            const float z4 = z2 * z2;
            const float z6 = z4 * z2;
            const float w2 = w * w;
            const float w3 = w2 * w;

            float* o = &sh[(tid & (CH - 1)) * NOUT];

            // m = 0
            o[0]  = sns[0];
            o[2]  = sns[2]  * z;
            o[6]  = sns[6]  * (z2 - 0.5f * w);
            o[12] = sns[12] * (z * (z2 - 1.5f * w));
            o[20] = sns[20] * (z4 - 3.f * w * z2 + 0.375f * w2);
            o[30] = sns[30] * (z * (z4 - 5.f * w * z2 + 1.875f * w2));
            o[42] = sns[42] * (z6 - 7.5f * w * z4 + 5.625f * w2 * z2 - 0.3125f * w3);

            // m = 1
            {
                const float P21 = 2.f * z;
                const float P31 = 3.f * z2 - 0.75f * w;
                const float P41 = z * (4.f * z2 - 3.f * w);
                const float P51 = 5.f * z4 - 7.5f * w * z2 + 0.625f * w2;
                const float P61 = z * (6.f * z4 - 15.f * w * z2 + 3.75f * w2);
                o[1]  = sns[1]  * y;
                o[3]  = sns[3]  * x;
                o[5]  = sns[5]  * (P21 * y);
                o[7]  = sns[7]  * (P21 * x);
                o[11] = sns[11] * (P31 * y);
                o[13] = sns[13] * (P31 * x);
                o[19] = sns[19] * (P41 * y);
                o[21] = sns[21] * (P41 * x);
                o[29] = sns[29] * (P51 * y);
                o[31] = sns[31] * (P51 * x);
                o[41] = sns[41] * (P61 * y);
                o[43] = sns[43] * (P61 * x);
            }

            // m = 2
            const float A2 = x * x - y * y;
            const float B2 = 2.f * x * y;
            {
                const float P32 = 3.f * z;
                const float P42 = 6.f * z2 - w;
                const float P52 = z * (10.f * z2 - 5.f * w);
                const float P62 = 15.f * z4 - 15.f * w * z2 + 0.9375f * w2;
                o[4]  = sns[4]  * B2;
                o[8]  = sns[8]  * A2;
                o[10] = sns[10] * (P32 * B2);
                o[14] = sns[14] * (P32 * A2);
                o[18] = sns[18] * (P42 * B2);
                o[22] = sns[22] * (P42 * A2);
                o[28] = sns[28] * (P52 * B2);
                o[32] = sns[32] * (P52 * A2);
                o[40] = sns[40] * (P62 * B2);
                o[44] = sns[44] * (P62 * A2);
            }

            // m = 3
            const float A3 = x * A2 - y * B2;
            const float B3 = x * B2 + y * A2;
            {
                const float P43 = 4.f * z;
                const float P53 = 10.f * z2 - 1.25f * w;
                const float P63 = z * (20.f * z2 - 7.5f * w);
                o[9]  = sns[9]  * B3;
                o[15] = sns[15] * A3;
                o[17] = sns[17] * (P43 * B3);
                o[23] = sns[23] * (P43 * A3);
                o[27] = sns[27] * (P53 * B3);
                o[33] = sns[33] * (P53 * A3);
                o[39] = sns[39] * (P63 * B3);
                o[45] = sns[45] * (P63 * A3);
            }

            // m = 4
            const float A4 = x * A3 - y * B3;
            const float B4 = x * B3 + y * A3;
            {
                const float P54 = 5.f * z;
                const float P64 = 15.f * z2 - 1.5f * w;
                o[16] = sns[16] * B4;
                o[24] = sns[24] * A4;
                o[26] = sns[26] * (P54 * B4);
                o[34] = sns[34] * (P54 * A4);
                o[38] = sns[38] * (P64 * B4);
                o[46] = sns[46] * (P64 * A4);
            }

            // m = 5
            const float A5 = x * A4 - y * B4;
            const float B5 = x * B4 + y * A4;
            {
                const float P65 = 6.f * z;
                o[25] = sns[25] * B5;
                o[35] = sns[35] * A5;
                o[37] = sns[37] * (P65 * B5);
                o[47] = sns[47] * (P65 * A5);
            }

            // m = 6
            o[36] = sns[36] * (x * B5 + y * A5);
            o[48] = sns[48] * (x * A5 - y * B5);
        }
        __syncthreads();

        // ---- coalesced flush of this chunk ----
        const int chunk_base = base + r * CH;
        int cnt = N - chunk_base;
        if (cnt > CH) cnt = CH;
        if (cnt == CH) {
            // CH*NOUT = 3136 floats = 784 float4 ; 784 = 6*128 + 16
            const float4* s4 = (const float4*)sh;
            float4* o4 = (float4*)(out + (size_t)chunk_base * NOUT);
            #pragma unroll
            for (int k = 0; k < 6; k++)
                __stcs(o4 + tid + k * BLK, s4[tid + k * BLK]);
            if (tid < 16)
                __stcs(o4 + tid + 6 * BLK, s4[tid + 6 * BLK]);
        } else if (cnt > 0) {
            const int total = cnt * NOUT;
            const size_t ob = (size_t)chunk_base * NOUT;
            for (int i = tid; i < total; i += BLK) out[ob + i] = sh[i];
        }
        __syncthreads();
    }
}

extern "C" void kernel_launch(void* const* d_in, const int* in_sizes, int n_in,
                              void* d_out, int out_size)
{
    const float* xyz = (const float*)d_in[0];   // [N, 3] f32
    const float* ns  = (const float*)d_in[2];   // [49] f32 (ns_lms)
    float* out = (float*)d_out;                 // [N, 49] f32
    const int N = in_sizes[0] / 3;

    const int grid = (N + BLK - 1) / BLK;
    rsh_kernel<<<grid, BLK>>>(xyz, ns, out, N);
}

// round 4
// speedup vs baseline: 1.1616x; 1.0960x over previous
#include <cuda_runtime.h>
#include <cstdint>

// Real solid harmonics, max_l = 6, factored form:
//   out[l(l+1)+m] = ns[l(l+1)+m] * P_{l,|m|}(z, w) * (A_|m| or B_|m|)
// with w = x^2+y^2, A_m + i B_m = (x + i y)^m.
// Stage 128x49 outputs in shared, flush with one 1-D TMA bulk store.

#define BLK 128
#define NOUT 49
#define TILE_BYTES (BLK * NOUT * 4)   // 25088, multiple of 16

__device__ __forceinline__ uint32_t smem_u32(const void* p) {
    uint32_t a;
    asm("{ .reg .u64 t; cvta.to.shared.u64 t, %1; cvt.u32.u64 %0, t; }"
        : "=r"(a) : "l"(p));
    return a;
}

__global__ __launch_bounds__(BLK) void rsh_kernel(
    const float* __restrict__ xyz,
    const float* __restrict__ ns,
    float* __restrict__ out,
    int N)
{
    __shared__ float sh[BLK * NOUT];   // 25088 B output staging
    __shared__ float sns[NOUT];

    const int tid = threadIdx.x;
    const int base = blockIdx.x * BLK;
    const int pt = base + tid;

    if (tid < NOUT) sns[tid] = ns[tid];

    float x = 0.f, y = 0.f, z = 0.f;
    if (pt < N) {
        x = __ldg(&xyz[(size_t)pt * 3 + 0]);
        y = __ldg(&xyz[(size_t)pt * 3 + 1]);
        z = __ldg(&xyz[(size_t)pt * 3 + 2]);
    }
    __syncthreads();   // sns visible

    if (pt < N) {
        const float w  = x * x + y * y;
        const float z2 = z * z;
        const float z4 = z2 * z2;
        const float z6 = z4 * z2;
        const float w2 = w * w;
        const float w3 = w2 * w;

        float* o = &sh[tid * NOUT];    // stride 49 floats: conflict-free (odd)

        // m = 0
        o[0]  = sns[0];
        o[2]  = sns[2]  * z;
        o[6]  = sns[6]  * (z2 - 0.5f * w);
        o[12] = sns[12] * (z * (z2 - 1.5f * w));
        o[20] = sns[20] * (z4 - 3.f * w * z2 + 0.375f * w2);
        o[30] = sns[30] * (z * (z4 - 5.f * w * z2 + 1.875f * w2));
        o[42] = sns[42] * (z6 - 7.5f * w * z4 + 5.625f * w2 * z2 - 0.3125f * w3);

        // m = 1
        {
            const float P21 = 2.f * z;
            const float P31 = 3.f * z2 - 0.75f * w;
            const float P41 = z * (4.f * z2 - 3.f * w);
            const float P51 = 5.f * z4 - 7.5f * w * z2 + 0.625f * w2;
            const float P61 = z * (6.f * z4 - 15.f * w * z2 + 3.75f * w2);
            o[1]  = sns[1]  * y;
            o[3]  = sns[3]  * x;
            o[5]  = sns[5]  * (P21 * y);
            o[7]  = sns[7]  * (P21 * x);
            o[11] = sns[11] * (P31 * y);
            o[13] = sns[13] * (P31 * x);
            o[19] = sns[19] * (P41 * y);
            o[21] = sns[21] * (P41 * x);
            o[29] = sns[29] * (P51 * y);
            o[31] = sns[31] * (P51 * x);
            o[41] = sns[41] * (P61 * y);
            o[43] = sns[43] * (P61 * x);
        }

        // m = 2
        const float A2 = x * x - y * y;
        const float B2 = 2.f * x * y;
        {
            const float P32 = 3.f * z;
            const float P42 = 6.f * z2 - w;
            const float P52 = z * (10.f * z2 - 5.f * w);
            const float P62 = 15.f * z4 - 15.f * w * z2 + 0.9375f * w2;
            o[4]  = sns[4]  * B2;
            o[8]  = sns[8]  * A2;
            o[10] = sns[10] * (P32 * B2);
            o[14] = sns[14] * (P32 * A2);
            o[18] = sns[18] * (P42 * B2);
            o[22] = sns[22] * (P42 * A2);
            o[28] = sns[28] * (P52 * B2);
            o[32] = sns[32] * (P52 * A2);
            o[40] = sns[40] * (P62 * B2);
            o[44] = sns[44] * (P62 * A2);
        }

        // m = 3
        const float A3 = x * A2 - y * B2;
        const float B3 = x * B2 + y * A2;
        {
            const float P43 = 4.f * z;
            const float P53 = 10.f * z2 - 1.25f * w;
            const float P63 = z * (20.f * z2 - 7.5f * w);
            o[9]  = sns[9]  * B3;
            o[15] = sns[15] * A3;
            o[17] = sns[17] * (P43 * B3);
            o[23] = sns[23] * (P43 * A3);
            o[27] = sns[27] * (P53 * B3);
            o[33] = sns[33] * (P53 * A3);
            o[39] = sns[39] * (P63 * B3);
            o[45] = sns[45] * (P63 * A3);
        }

        // m = 4
        const float A4 = x * A3 - y * B3;
        const float B4 = x * B3 + y * A3;
        {
            const float P54 = 5.f * z;
            const float P64 = 15.f * z2 - 1.5f * w;
            o[16] = sns[16] * B4;
            o[24] = sns[24] * A4;
            o[26] = sns[26] * (P54 * B4);
            o[34] = sns[34] * (P54 * A4);
            o[38] = sns[38] * (P64 * B4);
            o[46] = sns[46] * (P64 * A4);
        }

        // m = 5
        const float A5 = x * A4 - y * B4;
        const float B5 = x * B4 + y * A4;
        {
            const float P65 = 6.f * z;
            o[25] = sns[25] * B5;
            o[35] = sns[35] * A5;
            o[37] = sns[37] * (P65 * B5);
            o[47] = sns[47] * (P65 * A5);
        }

        // m = 6
        o[36] = sns[36] * (x * B5 + y * A5);
        o[48] = sns[48] * (x * A5 - y * B5);
    }
    __syncthreads();

    int npts = N - base;
    if (npts >= BLK) {
        // Full tile: single TMA bulk store smem -> global (25088 B, 16B aligned).
        if (tid == 0) {
            asm volatile("fence.proxy.async.shared::cta;" ::: "memory");
            const uint64_t dst = (uint64_t)(uintptr_t)(out + (size_t)base * NOUT);
            const uint32_t src = smem_u32(sh);
            asm volatile(
                "cp.async.bulk.global.shared::cta.bulk_group [%0], [%1], %2;"
                :: "l"(dst), "r"(src), "r"((uint32_t)TILE_BYTES) : "memory");
            asm volatile("cp.async.bulk.commit_group;" ::: "memory");
            // Keep CTA (and its smem) alive until the bulk read completes.
            asm volatile("cp.async.bulk.wait_group 0;" ::: "memory");
        }
    } else if (npts > 0) {
        // Tail block: scalar coalesced flush.
        const int total = npts * NOUT;
        const size_t ob = (size_t)base * NOUT;
        for (int i = tid; i < total; i += BLK) out[ob + i] = sh[i];
    }
}

extern "C" void kernel_launch(void* const* d_in, const int* in_sizes, int n_in,
                              void* d_out, int out_size)
{
    const float* xyz = (const float*)d_in[0];   // [N, 3] f32
    const float* ns  = (const float*)d_in[2];   // [49] f32 (ns_lms)
    float* out = (float*)d_out;                 // [N, 49] f32
    const int N = in_sizes[0] / 3;

    const int grid = (N + BLK - 1) / BLK;
    rsh_kernel<<<grid, BLK>>>(xyz, ns, out, N);
}